// round 16
// baseline (speedup 1.0000x reference)
#include <cuda_runtime.h>
#include <cuda_bf16.h>
#include <math.h>
#include <stdint.h>

#define NN 100000
#define DD 128
#define NE 800000
#define BMT 32
#define NTILES (NN / BMT)               // 3125, exact
#define KPAD 264
#define GEMM_GRID 148
#define GEMM_THR 512
#define PRE_GRID 148
#define PRE_THR  1024
#define CHUNK 676                       // 148*676 = 100048 >= NN

// ---------------------------------------------------------------------------
__device__ float g_sum[DD];
__device__ float g_sumsq[DD];
__device__ int   g_cnt[NN];
__device__ int   g_ptr[NN + 1];
__device__ int   g_cur[NN];
__device__ int   g_csrc[NE];
__device__ int   g_bsum[PRE_GRID];
__device__ unsigned g_barv;
__device__ unsigned g_done;

// ---------------------------------------------------------------------------
__device__ __forceinline__ uint32_t smem_to_u32(const void* p) {
    uint32_t a;
    asm("{ .reg .u64 t; cvta.to.shared.u64 t, %1; cvt.u32.u64 %0, t; }"
        : "=r"(a) : "l"(p));
    return a;
}
#define LDSM_X4(r, addr) \
    asm volatile("ldmatrix.sync.aligned.m8n8.x4.shared.b16 {%0,%1,%2,%3}, [%4];" \
        : "=r"((r)[0]), "=r"((r)[1]), "=r"((r)[2]), "=r"((r)[3]) : "r"(addr))
#define MMA16816(c, a, b0, b1) \
    asm volatile("mma.sync.aligned.m16n8k16.row.col.f32.bf16.bf16.f32 " \
        "{%0,%1,%2,%3}, {%4,%5,%6,%7}, {%8,%9}, {%0,%1,%2,%3};" \
        : "+f"((c)[0]), "+f"((c)[1]), "+f"((c)[2]), "+f"((c)[3]) \
        : "r"((a)[0]), "r"((a)[1]), "r"((a)[2]), "r"((a)[3]), "r"(b0), "r"(b1))

// ---------------------------------------------------------------------------
// software global barrier (single co-resident wave; counters reset at exit)
__device__ __forceinline__ void gbar(unsigned target) {
    __syncthreads();
    __threadfence();
    if (threadIdx.x == 0) {
        atomicAdd(&g_barv, 1u);
        while (atomicAdd(&g_barv, 0u) < target) {}
    }
    __syncthreads();
}

__device__ __forceinline__ int block_scan_excl(int v, int* ws, int& total) {
    int lane = threadIdx.x & 31;
    int w = threadIdx.x >> 5;
    int x = v;
#pragma unroll
    for (int o = 1; o < 32; o <<= 1) {
        int t = __shfl_up_sync(0xFFFFFFFFu, x, o);
        if (lane >= o) x += t;
    }
    if (lane == 31) ws[w] = x;
    __syncthreads();
    if (w == 0) {
        int y = ws[lane];
#pragma unroll
        for (int o = 1; o < 32; o <<= 1) {
            int t = __shfl_up_sync(0xFFFFFFFFu, y, o);
            if (lane >= o) y += t;
        }
        ws[lane] = y;
    }
    __syncthreads();
    int incl = x + (w > 0 ? ws[w - 1] : 0);
    total = ws[31];
    return incl - v;
}

// ---------------------------------------------------------------------------
// ONE persistent kernel for all pre-work: stats + count -> scan -> scatter.
__global__ void __launch_bounds__(PRE_THR, 1)
k_prework(const float* __restrict__ feat,
          const int* __restrict__ src,
          const int* __restrict__ dst) {
    __shared__ float rs[32 * 128];
    __shared__ float rq[32 * 128];
    __shared__ int ws[32];
    const int tid = threadIdx.x;
    const int cta = blockIdx.x;

    // ---- phase 1a: column stats
    {
        int cg = tid & 31;
        int rg = tid >> 5;
        float s[4] = {0.f, 0.f, 0.f, 0.f};
        float q[4] = {0.f, 0.f, 0.f, 0.f};
        for (int r = cta * 32 + rg; r < NN; r += PRE_GRID * 32) {
            float4 v = reinterpret_cast<const float4*>(feat + (size_t)r * DD)[cg];
            s[0] += v.x; q[0] += v.x * v.x;
            s[1] += v.y; q[1] += v.y * v.y;
            s[2] += v.z; q[2] += v.z * v.z;
            s[3] += v.w; q[3] += v.w * v.w;
        }
#pragma unroll
        for (int j = 0; j < 4; j++) {
            rs[rg * 128 + cg * 4 + j] = s[j];
            rq[rg * 128 + cg * 4 + j] = q[j];
        }
        __syncthreads();
        if (tid < 128) {
            float ts = 0.f, tq = 0.f;
#pragma unroll
            for (int g = 0; g < 32; g++) {
                ts += rs[g * 128 + tid];
                tq += rq[g * 128 + tid];
            }
            atomicAdd(&g_sum[tid], ts);
            atomicAdd(&g_sumsq[tid], tq);
        }
    }
    // ---- phase 1b: degree count
    for (int i = cta * PRE_THR + tid; i < NE; i += PRE_GRID * PRE_THR)
        atomicAdd(&g_cnt[dst[i]], 1);

    gbar(1 * PRE_GRID);

    // ---- phase 2: per-CTA chunk scan of g_cnt (re-zeroing it)
    const int gi = cta * CHUNK + tid;
    {
        int v = (tid < CHUNK && gi < NN) ? g_cnt[gi] : 0;
        if (tid < CHUNK && gi < NN) g_cnt[gi] = 0;
        int total;
        int ex = block_scan_excl(v, ws, total);
        if (tid < CHUNK && gi < NN) g_ptr[gi] = ex;
        if (tid == 0) g_bsum[cta] = total;
    }
    gbar(2 * PRE_GRID);

    // ---- phase 3: CTA0 scans the chunk sums
    if (cta == 0) {
        int v = (tid < PRE_GRID) ? g_bsum[tid] : 0;
        int total;
        int ex = block_scan_excl(v, ws, total);
        if (tid < PRE_GRID) g_bsum[tid] = ex;
    }
    gbar(3 * PRE_GRID);

    // ---- phase 4: apply chunk offsets
    if (tid < CHUNK && gi < NN) {
        int p = g_ptr[gi] + g_bsum[cta];
        g_ptr[gi] = p;
        g_cur[gi] = p;
    }
    if (cta == 0 && tid == 0) g_ptr[NN] = NE;
    gbar(4 * PRE_GRID);

    // ---- phase 5: CSR scatter
    for (int i = cta * PRE_THR + tid; i < NE; i += PRE_GRID * PRE_THR) {
        int pos = atomicAdd(&g_cur[dst[i]], 1);
        g_csrc[pos] = src[i];
    }

    // ---- exit protocol: reset barrier counters for the next graph replay
    __syncthreads();
    if (tid == 0) {
        atomicAdd(&g_done, 1u);
        if (cta == 0) {
            while (atomicAdd(&g_done, 0u) < PRE_GRID) {}
            g_barv = 0;
            g_done = 0;
            __threadfence();
        }
    }
}

// ---------------------------------------------------------------------------
// bf16x3 mma.sync GEMM, BMT=32 with DOUBLE-BUFFERED A and ONE barrier per
// tile: fast warps run up to a full tile ahead of gather-tail stragglers.
// On-the-fly BatchNorm affine; batched (MLP=4) CSR gather; direct-STG.
__device__ __forceinline__ float gelu_exact(float x) {
    return 0.5f * x * (1.f + erff(x * 0.70710678118654752f));
}
__device__ __forceinline__ uint32_t pack_bf16x2(__nv_bfloat16 lo, __nv_bfloat16 hi) {
    __nv_bfloat162 p(lo, hi);
    return *reinterpret_cast<uint32_t*>(&p);
}

#define APLANE  (BMT * KPAD * 2)            // 16896 B
#define SM_BHI  0
#define SM_BLO  (SM_BHI + DD * KPAD * 2)    // 67584
#define SM_AB   (SM_BLO + DD * KPAD * 2)    // 135168; buf b: hi at b*2*APLANE, lo +APLANE
#define SM_BIAS (SM_AB + 4 * APLANE)        // 202752
#define SM_ISG  (SM_BIAS + 512)             // 203264
#define SM_OFF  (SM_ISG + 512)              // 203776
#define SM_TOT  (SM_OFF + 512)              // 204288

__global__ void __launch_bounds__(GEMM_THR, 1)
k_gemm_mma(const float* __restrict__ feat,
           const float* __restrict__ gamma,
           const float* __restrict__ beta,
           const float* __restrict__ Wself,
           const float* __restrict__ Wneigh,
           const float* __restrict__ bias,
           float* __restrict__ out) {
    extern __shared__ char smem[];
    const uint32_t smem_base = smem_to_u32(smem);
    const int tid  = threadIdx.x;
    const int wid  = tid >> 5;
    const int lane = tid & 31;

    // ---- BN affine constants
    if (tid < DD) {
        const float invN = 1.f / (float)NN;
        float mean = g_sum[tid] * invN;
        float var  = fmaxf(g_sumsq[tid] * invN - mean * mean, 0.f);
        float is   = rsqrtf(var + 1e-5f) * gamma[tid];
        reinterpret_cast<float*>(smem + SM_ISG)[tid] = is;
        reinterpret_cast<float*>(smem + SM_OFF)[tid] = beta[tid] - mean * is;
        reinterpret_cast<float*>(smem + SM_BIAS)[tid] = bias[tid];
    }

    // ---- stage B once: transpose, +I fold, bf16 hi/lo split
    for (int i = 0; i < 16; i++) {
        int e = tid + i * GEMM_THR;
        int k = e >> 5;
        int c4 = e & 31;
        const float4* wr = (k < DD)
            ? reinterpret_cast<const float4*>(Wself  + (size_t)k * DD)
            : reinterpret_cast<const float4*>(Wneigh + (size_t)(k - DD) * DD);
        float4 w = wr[c4];
        float wv[4] = {w.x, w.y, w.z, w.w};
#pragma unroll
        for (int j = 0; j < 4; j++) {
            int n = c4 * 4 + j;
            float vv = wv[j] + ((k < DD && n == k) ? 1.0f : 0.0f);
            __nv_bfloat16 hi = __float2bfloat16(vv);
            __nv_bfloat16 lo = __float2bfloat16(vv - __bfloat162float(hi));
            uint32_t off = ((uint32_t)n * KPAD + (uint32_t)k) * 2u;
            *reinterpret_cast<__nv_bfloat16*>(smem + SM_BHI + off) = hi;
            *reinterpret_cast<__nv_bfloat16*>(smem + SM_BLO + off) = lo;
        }
    }

    const float* bias_s = reinterpret_cast<const float*>(smem + SM_BIAS);
    const float* isg_s  = reinterpret_cast<const float*>(smem + SM_ISG);
    const float* off_s  = reinterpret_cast<const float*>(smem + SM_OFF);
    const int wr2 = wid >> 3;               // row group: rows wr2*16..+15
    const int wc  = wid & 7;                // col group: cols wc*16..+15
    const int a_row_l = lane & 15;
    const int a_k_l   = (lane >> 4) << 3;
    const int b_n_l   = ((lane >> 4) << 3) + (lane & 7);
    const int b_k_l   = ((lane >> 3) & 1) << 3;
    const int lr0 = wid * 2;                // this warp's 2 gather rows

    float4 v[2];                            // raw feat prefetch (h half)
    float4 acc[2];                          // raw neighbor sums
    int    dg[2];

    // batched (MLP=4) per-row gather into acc[]
    auto do_gather = [&](int row0) {
#pragma unroll
        for (int j = 0; j < 2; j++) {
            int gr = row0 + lr0 + j;
            int e  = g_ptr[gr];
            int en = g_ptr[gr + 1];
            dg[j] = en - e;
            float4 a = make_float4(0.f, 0.f, 0.f, 0.f);
            for (; e + 4 <= en; e += 4) {
                int s0 = g_csrc[e],     s1 = g_csrc[e + 1];
                int s2 = g_csrc[e + 2], s3 = g_csrc[e + 3];
                float4 t0 = reinterpret_cast<const float4*>(feat + (size_t)s0 * DD)[lane];
                float4 t1 = reinterpret_cast<const float4*>(feat + (size_t)s1 * DD)[lane];
                float4 t2 = reinterpret_cast<const float4*>(feat + (size_t)s2 * DD)[lane];
                float4 t3 = reinterpret_cast<const float4*>(feat + (size_t)s3 * DD)[lane];
                a.x += t0.x + t1.x + t2.x + t3.x;
                a.y += t0.y + t1.y + t2.y + t3.y;
                a.z += t0.z + t1.z + t2.z + t3.z;
                a.w += t0.w + t1.w + t2.w + t3.w;
            }
            for (; e < en; e++) {
                int s = g_csrc[e];
                float4 t = reinterpret_cast<const float4*>(feat + (size_t)s * DD)[lane];
                a.x += t.x; a.y += t.y; a.z += t.z; a.w += t.w;
            }
            acc[j] = a;
        }
    };

    // ---- prologue: gather + h prefetch for the first tile
    int tile = blockIdx.x;
    {
        const int row0 = tile * BMT;
        do_gather(row0);
#pragma unroll
        for (int i = 0; i < 2; i++) {
            int e = tid + i * GEMM_THR;     // 0..1023
            int r  = e >> 5;                // 0..31
            int c4 = e & 31;
            v[i] = reinterpret_cast<const float4*>(feat + (size_t)(row0 + r) * DD)[c4];
        }
    }

    int it = 0;
    for (; tile < NTILES; tile += GEMM_GRID, it++) {
        const int row0 = tile * BMT;
        const int nxt  = tile + GEMM_GRID;
        const int buf = it & 1;
        const uint32_t a_hi_off = SM_AB + (uint32_t)buf * 2 * APLANE;
        const uint32_t a_lo_off = a_hi_off + APLANE;

        // ---- convert gathered means -> A-neigh (cols 128..255) of buf
#pragma unroll
        for (int j = 0; j < 2; j++) {
            float iv  = (dg[j] > 0) ? 1.f / (float)dg[j] : 0.f;
            float ofm = (dg[j] > 0) ? 1.f : 0.f;
            float a4[4] = {acc[j].x, acc[j].y, acc[j].z, acc[j].w};
            __nv_bfloat16 h[4], l[4];
#pragma unroll
            for (int q = 0; q < 4; q++) {
                int col = lane * 4 + q;
                float x = a4[q] * isg_s[col] * iv + off_s[col] * ofm;
                h[q] = __float2bfloat16(x);
                l[q] = __float2bfloat16(x - __bfloat162float(h[q]));
            }
            uint32_t boff = ((uint32_t)(lr0 + j) * KPAD + 128u
                             + (uint32_t)lane * 4u) * 2u;
            *reinterpret_cast<uint2*>(smem + a_hi_off + boff) =
                make_uint2(pack_bf16x2(h[0], h[1]), pack_bf16x2(h[2], h[3]));
            *reinterpret_cast<uint2*>(smem + a_lo_off + boff) =
                make_uint2(pack_bf16x2(l[0], l[1]), pack_bf16x2(l[2], l[3]));
        }
        // ---- convert raw h regs -> A (cols 0..127) of buf
#pragma unroll
        for (int i = 0; i < 2; i++) {
            int e = tid + i * GEMM_THR;
            int r  = e >> 5;
            int c4 = e & 31;
            float x4[4] = {v[i].x, v[i].y, v[i].z, v[i].w};
            __nv_bfloat16 h[4], l[4];
#pragma unroll
            for (int j = 0; j < 4; j++) {
                int col = c4 * 4 + j;
                float x = x4[j] * isg_s[col] + off_s[col];
                h[j] = __float2bfloat16(x);
                l[j] = __float2bfloat16(x - __bfloat162float(h[j]));
            }
            uint32_t boff = ((uint32_t)r * KPAD + (uint32_t)c4 * 4) * 2u;
            *reinterpret_cast<uint2*>(smem + a_hi_off + boff) =
                make_uint2(pack_bf16x2(h[0], h[1]), pack_bf16x2(h[2], h[3]));
            *reinterpret_cast<uint2*>(smem + a_lo_off + boff) =
                make_uint2(pack_bf16x2(l[0], l[1]), pack_bf16x2(l[2], l[3]));
        }

        __syncthreads();   // buf FULL for all; prior iter (buf^1 k-loop) done

        // ---- prefetch next tile's h half (lands during the k-loop)
        if (nxt < NTILES) {
            const int nrow0 = nxt * BMT;
#pragma unroll
            for (int i = 0; i < 2; i++) {
                int e = tid + i * GEMM_THR;
                int r  = e >> 5;
                int c4 = e & 31;
                v[i] = reinterpret_cast<const float4*>(
                           feat + (size_t)(nrow0 + r) * DD)[c4];
            }
        }

        float c[2][4];
#pragma unroll
        for (int nt = 0; nt < 2; nt++)
#pragma unroll
            for (int q = 0; q < 4; q++) c[nt][q] = 0.f;

#pragma unroll 4
        for (int ks = 0; ks < 16; ks++) {
            const int k0 = ks * 16;
            uint32_t a_hi[4], a_lo[4], b_hi[4], b_lo[4];
            {
                uint32_t ao = (uint32_t)((wr2 * 16 + a_row_l) * KPAD
                                         + k0 + a_k_l) * 2u;
                LDSM_X4(a_hi, smem_base + a_hi_off + ao);
                LDSM_X4(a_lo, smem_base + a_lo_off + ao);
            }
            {
                uint32_t bo = (uint32_t)((wc * 16 + b_n_l) * KPAD
                                         + k0 + b_k_l) * 2u;
                LDSM_X4(b_hi, smem_base + SM_BHI + bo);
                LDSM_X4(b_lo, smem_base + SM_BLO + bo);
            }
#pragma unroll
            for (int nt = 0; nt < 2; nt++)
                MMA16816(c[nt], a_hi, b_hi[2 * nt], b_hi[2 * nt + 1]);
#pragma unroll
            for (int nt = 0; nt < 2; nt++)
                MMA16816(c[nt], a_hi, b_lo[2 * nt], b_lo[2 * nt + 1]);
#pragma unroll
            for (int nt = 0; nt < 2; nt++)
                MMA16816(c[nt], a_lo, b_hi[2 * nt], b_hi[2 * nt + 1]);
        }

        // ---- gather next tile (overlaps peers' k-loops; no barrier below)
        if (nxt < NTILES) do_gather(nxt * BMT);

        // ---- epilogue: bias + exact GELU + direct fragment stores
        {
            int rbase = row0 + wr2 * 16 + (lane >> 2);
#pragma unroll
            for (int nt = 0; nt < 2; nt++) {
                int col = wc * 16 + nt * 8 + 2 * (lane & 3);
                float b0 = bias_s[col], b1 = bias_s[col + 1];
                float2 o0 = make_float2(gelu_exact(c[nt][0] + b0),
                                        gelu_exact(c[nt][1] + b1));
                *reinterpret_cast<float2*>(out + (size_t)rbase * DD + col) = o0;
                float2 o1 = make_float2(gelu_exact(c[nt][2] + b0),
                                        gelu_exact(c[nt][3] + b1));
                *reinterpret_cast<float2*>(out + (size_t)(rbase + 8) * DD + col) = o1;
            }
        }
        // no second barrier: next iteration writes buf^1, whose readers all
        // passed this iteration's __syncthreads() already.
    }

    // re-arm stats for the next graph replay
    if (blockIdx.x == 0 && tid < DD) { g_sum[tid] = 0.f; g_sumsq[tid] = 0.f; }
}

// ---------------------------------------------------------------------------
extern "C" void kernel_launch(void* const* d_in, const int* in_sizes, int n_in,
                              void* d_out, int out_size) {
    const float* features = (const float*)d_in[0];
    const int*   src      = (const int*)d_in[1];
    const int*   dst      = (const int*)d_in[2];
    const float* gamma    = (const float*)d_in[3];
    const float* beta     = (const float*)d_in[4];
    const float* W_self   = (const float*)d_in[5];
    const float* W_neigh  = (const float*)d_in[6];
    const float* b        = (const float*)d_in[7];
    float* out = (float*)d_out;

    cudaFuncSetAttribute(k_gemm_mma, cudaFuncAttributeMaxDynamicSharedMemorySize, SM_TOT);

    k_prework<<<PRE_GRID, PRE_THR>>>(features, src, dst);
    k_gemm_mma<<<GEMM_GRID, GEMM_THR, SM_TOT>>>(features, gamma, beta,
                                                W_self, W_neigh, b, out);
}